// round 15
// baseline (speedup 1.0000x reference)
#include <cuda_runtime.h>
#include <math.h>

#define B_  32
#define H_  512
#define W_  512
#define DEG 0.017453292519943295f
#define NT  256     // 8 warps; warp w handles rows [w*8, w*8+8) of a 32x64 tile

__device__ __forceinline__ float frcp_nr(float x) {
    float y;
    asm("rcp.approx.f32 %0, %1;" : "=f"(y) : "f"(x));
    return y * fmaf(-x, y, 2.0f);   // one Newton step -> ~1 ulp
}
__device__ __forceinline__ float flg2(float x) {
    float y;
    asm("lg2.approx.f32 %0, %1;" : "=f"(y) : "f"(x));
    return y;
}
__device__ __forceinline__ float fex2(float x) {
    float y;
    asm("ex2.approx.f32 %0, %1;" : "=f"(y) : "f"(x));
    return y;
}

// Taylor sin/cos for |x| <= 0.262 rad: err ~1.6e-8 / 4e-10 -- better than sinf.
__device__ __forceinline__ void sincos_small(float x, float* s, float* c) {
    float x2 = x * x;
    *s = x * fmaf(x2, fmaf(x2, fmaf(x2, -1.984126984e-4f, 8.333333333e-3f),
                           -1.666666667e-1f), 1.f);
    *c = fmaf(x2, fmaf(x2, fmaf(x2, -1.388888889e-3f, 4.166666667e-2f),
                       -5.e-1f), 1.f);
}

__device__ __forceinline__ void mat3_mul(const float* A, const float* Bm, float* C) {
#pragma unroll
    for (int i = 0; i < 3; i++)
#pragma unroll
        for (int j = 0; j < 3; j++) {
            float s = 0.f;
#pragma unroll
            for (int k = 0; k < 3; k++) s += A[i * 3 + k] * Bm[k * 3 + j];
            C[i * 3 + j] = s;
        }
}

// Per-block param computation (thread 0); ~120 instrs, hidden by other
// resident blocks. Layout: 0..8 M, 9 gamma, 10..18 Mc,
// 19 jlo, 20 jhi, 21 ilo, 22 ihi (pixel-space cutout bounds, exclusive <)
__device__ void compute_params(int b,
                               const float* __restrict__ geom_u,
                               const float* __restrict__ color_u,
                               const float* __restrict__ cutout_u,
                               float* __restrict__ p) {
    const float* g = geom_u + b * 8;
    float flip = g[0] > 0.5f ? -1.f : 1.f;
    float tilt = (g[1] * 2.f - 1.f) * (15.f * DEG);
    float pan  = (g[2] * 2.f - 1.f) * (15.f * DEG);
    float rot  = (g[3] * 2.f - 1.f) * (15.f * DEG);
    float sc   = 1.f + (g[4] * 2.f - 1.f) * 0.1f;
    float tx   = (g[5] * 2.f - 1.f) * 0.2f;
    float ty   = (g[6] * 2.f - 1.f) * 0.2f;

    float ct, st, cp, sp, cr, sr;
    sincos_small(tilt, &st, &ct);
    sincos_small(pan, &sp, &cp);
    sincos_small(rot, &sr, &cr);

    float F[9]  = {flip, 0, 0, 0, 1, 0, 0, 0, 1};
    float Rx[9] = {1, 0, 0, 0, ct, -st, 0, st, ct};
    float Ry[9] = {cp, 0, sp, 0, 1, 0, -sp, 0, cp};
    float RS[9] = {sc * cr, -sc * sr, 0, sc * sr, sc * cr, 0, 0, 0, 1};
    float T[9]  = {1, 0, tx, 0, 1, ty, 0, 0, 1};

    float t0[9], t1[9], t2[9], M[9];
    mat3_mul(Ry, F, t0);
    mat3_mul(Rx, t0, t1);
    mat3_mul(RS, t1, t2);
    mat3_mul(T, t2, M);

    const float* c = color_u + b * 4;
    float theta = (c[0] * 2.f - 1.f) * (10.f * DEG);
    float cth, sth;
    sincos_small(theta, &sth, &cth);
    const float a = 0.5773502691896258f;
    float K[9] = {0, -a, a, a, 0, -a, -a, a, 0};
    float Rh[9];
#pragma unroll
    for (int i = 0; i < 3; i++)
#pragma unroll
        for (int j = 0; j < 3; j++)
            Rh[i * 3 + j] = cth * (i == j ? 1.f : 0.f) + sth * K[i * 3 + j] +
                            (1.f - cth) * (1.f / 3.f);
    float sat = 1.f + (c[1] * 2.f - 1.f) * 0.4f;
    const float lum[3] = {0.299f, 0.587f, 0.114f};
    float Sm[9];
#pragma unroll
    for (int i = 0; i < 3; i++)
#pragma unroll
        for (int j = 0; j < 3; j++)
            Sm[i * 3 + j] = sat * (i == j ? 1.f : 0.f) + (1.f - sat) * lum[j];
    float bright = 1.f + (c[2] * 2.f - 1.f) * 0.1f;
    float Mc[9];
    mat3_mul(Sm, Rh, Mc);
#pragma unroll
    for (int i = 0; i < 9; i++) Mc[i] *= bright;
    float gamma = 1.f + (c[3] * 2.f - 1.f) * 0.2f;

    const float* cu = cutout_u + b * 5;
    bool apply = (cu[0] < 0.5f);
    float cwh = (0.3f + 0.2f * cu[3]) * 0.5f * 511.f;
    float chh = (0.3f + 0.2f * cu[4]) * 0.5f * 511.f;
    float ccx = cu[1] * 511.f, ccy = cu[2] * 511.f;
#pragma unroll
    for (int i = 0; i < 9; i++) p[i] = M[i];
    p[9] = gamma;
#pragma unroll
    for (int i = 0; i < 9; i++) p[10 + i] = Mc[i];
    p[19] = apply ? (ccx - cwh) : 1e9f;   // jlo (never satisfied if !apply)
    p[20] = apply ? (ccx + cwh) : -1e9f;  // jhi
    p[21] = ccy - chh;                    // ilo
    p[22] = ccy + chh;                    // ihi
}

__global__ __launch_bounds__(NT, 6) void augment_main(
    const float* __restrict__ images, float* __restrict__ out,
    const float* __restrict__ geom_u, const float* __restrict__ color_u,
    const float* __restrict__ cutout_u) {
    __shared__ float spm[24];

    int b   = blockIdx.z;
    int tid = threadIdx.x;
    if (tid == 0) compute_params(b, geom_u, color_u, cutout_u, spm);
    __syncthreads();

    int lane = tid & 31;
    int w    = tid >> 5;
    int jx   = (blockIdx.x << 5) + lane;       // x (consecutive across warp)
    int iy0  = (blockIdx.y << 6) + (w << 3);   // first of 8 rows

    float m0 = spm[0], m1 = spm[1], m2 = spm[2];
    float m3 = spm[3], m4 = spm[4], m5 = spm[5];
    float m6 = spm[6], m7 = spm[7], m8 = spm[8];
    float gamma = spm[9];
    float c0 = spm[10], c1 = spm[11], c2 = spm[12];
    float c3 = spm[13], c4 = spm[14], c5 = spm[15];
    float c6 = spm[16], c7 = spm[17], c8 = spm[18];
    float jlo = spm[19], jhi = spm[20];
    float ilo = spm[21], ihi = spm[22];

    const float cc = 2.f / 511.f;
    float fjx = (float)jx;
    float X = fjx * cc - 1.f;
    float sxX = fmaf(m0, X, m2);
    float syX = fmaf(m3, X, m5);
    float szX = fmaf(m6, X, m8);

    bool cutx = (fjx > jlo) & (fjx < jhi);

    int bOff = b << 18;
    int outBase = ((bOff + (iy0 << 9)) + jx) * 3;

    float Y   = (float)iy0 * cc - 1.f;
    float fiy = (float)iy0;

#pragma unroll
    for (int k = 0; k < 8; k++) {
        float sx = fmaf(m1, Y, sxX);
        float sy = fmaf(m4, Y, syX);
        float sz = fmaf(m7, Y, szX);
        float inv = frcp_nr(sz);
        float px = fmaf(sx * inv, 255.5f, 255.5f);
        float py = fmaf(sy * inv, 255.5f, 255.5f);

        bool valid = (px >= 0.f) & (px <= 511.f) & (py >= 0.f) & (py <= 511.f);
        int x0 = min(max(__float2int_rd(px), 0), 511);
        int y0 = min(max(__float2int_rd(py), 0), 511);
        float wx = px - (float)x0;
        float wy = py - (float)y0;
        int dx3 = (x0 < 511) ? 3 : 0;
        int dyW = (y0 < 511) ? (W_ * 3) : 0;

        const float* A  = images + (bOff + (y0 << 9) + x0) * 3;
        const float* Bt = A + dyW;

        float a00 = __ldg(A + 0),        a01 = __ldg(A + 1),        a02 = __ldg(A + 2);
        float b00 = __ldg(A + dx3 + 0),  b01 = __ldg(A + dx3 + 1),  b02 = __ldg(A + dx3 + 2);
        float d00 = __ldg(Bt + 0),       d01 = __ldg(Bt + 1),       d02 = __ldg(Bt + 2);
        float e00 = __ldg(Bt + dx3 + 0), e01 = __ldg(Bt + dx3 + 1), e02 = __ldg(Bt + dx3 + 2);

        float omx = 1.f - wx, omy = 1.f - wy;
        float w00 = omx * omy, w01 = wx * omy, w10 = omx * wy, w11 = wx * wy;
        float vm = valid ? 1.f : 0.f;

        float r0 = a00 * w00 + b00 * w01 + d00 * w10 + e00 * w11;
        float r1 = a01 * w00 + b01 * w01 + d01 * w10 + e01 * w11;
        float r2 = a02 * w00 + b02 * w01 + d02 * w10 + e02 * w11;
        r0 = __saturatef(r0 * vm);
        r1 = __saturatef(r1 * vm);
        r2 = __saturatef(r2 * vm);
        r0 = fex2(gamma * flg2(r0));   // 0 -> ex2(-inf) = 0 == 0^g
        r1 = fex2(gamma * flg2(r1));
        r2 = fex2(gamma * flg2(r2));

        float o0 = __saturatef(c0 * r0 + c1 * r1 + c2 * r2);
        float o1 = __saturatef(c3 * r0 + c4 * r1 + c5 * r2);
        float o2 = __saturatef(c6 * r0 + c7 * r1 + c8 * r2);

        bool cut = cutx & (fiy > ilo) & (fiy < ihi);
        if (cut) { o0 = 0.f; o1 = 0.f; o2 = 0.f; }

        float* op = out + outBase;
        op[0] = o0;
        op[1] = o1;
        op[2] = o2;

        Y += cc;
        fiy += 1.f;
        outBase += W_ * 3;
    }
}

extern "C" void kernel_launch(void* const* d_in, const int* in_sizes, int n_in,
                              void* d_out, int out_size) {
    const float* images   = (const float*)d_in[0];
    const float* geom_u   = (const float*)d_in[1];
    const float* color_u  = (const float*)d_in[2];
    const float* cutout_u = (const float*)d_in[3];
    float* out = (float*)d_out;

    dim3 grid(W_ / 32, H_ / 64, B_);
    augment_main<<<grid, NT>>>(images, out, geom_u, color_u, cutout_u);
}

// round 16
// speedup vs baseline: 1.0597x; 1.0597x over previous
#include <cuda_runtime.h>
#include <math.h>

#define B_  32
#define H_  512
#define W_  512
#define DEG 0.017453292519943295f
#define NT  256     // 8 warps; warp w handles rows [w*4, w*4+4) of a 32x32 tile

__device__ __forceinline__ float frcp_nr(float x) {
    float y;
    asm("rcp.approx.f32 %0, %1;" : "=f"(y) : "f"(x));
    return y * fmaf(-x, y, 2.0f);   // one Newton step -> ~1 ulp
}
__device__ __forceinline__ float flg2(float x) {
    float y;
    asm("lg2.approx.f32 %0, %1;" : "=f"(y) : "f"(x));
    return y;
}
__device__ __forceinline__ float fex2(float x) {
    float y;
    asm("ex2.approx.f32 %0, %1;" : "=f"(y) : "f"(x));
    return y;
}

// Taylor sin/cos for |x| <= 0.262 rad: err ~1.6e-8 / 4e-10 -- better than sinf.
__device__ __forceinline__ void sincos_small(float x, float* s, float* c) {
    float x2 = x * x;
    *s = x * fmaf(x2, fmaf(x2, fmaf(x2, -1.984126984e-4f, 8.333333333e-3f),
                           -1.666666667e-1f), 1.f);
    *c = fmaf(x2, fmaf(x2, fmaf(x2, -1.388888889e-3f, 4.166666667e-2f),
                       -5.e-1f), 1.f);
}

__device__ __forceinline__ void mat3_mul(const float* A, const float* Bm, float* C) {
#pragma unroll
    for (int i = 0; i < 3; i++)
#pragma unroll
        for (int j = 0; j < 3; j++) {
            float s = 0.f;
#pragma unroll
            for (int k = 0; k < 3; k++) s += A[i * 3 + k] * Bm[k * 3 + j];
            C[i * 3 + j] = s;
        }
}

// Per-block param computation (thread 0); ~120 instrs, hidden by other
// resident blocks. Layout: 0..8 M, 9 gamma, 10..18 Mc,
// 19 jlo, 20 jhi, 21 ilo, 22 ihi (pixel-space cutout bounds, exclusive <)
__device__ void compute_params(int b,
                               const float* __restrict__ geom_u,
                               const float* __restrict__ color_u,
                               const float* __restrict__ cutout_u,
                               float* __restrict__ p) {
    const float* g = geom_u + b * 8;
    float flip = g[0] > 0.5f ? -1.f : 1.f;
    float tilt = (g[1] * 2.f - 1.f) * (15.f * DEG);
    float pan  = (g[2] * 2.f - 1.f) * (15.f * DEG);
    float rot  = (g[3] * 2.f - 1.f) * (15.f * DEG);
    float sc   = 1.f + (g[4] * 2.f - 1.f) * 0.1f;
    float tx   = (g[5] * 2.f - 1.f) * 0.2f;
    float ty   = (g[6] * 2.f - 1.f) * 0.2f;

    float ct, st, cp, sp, cr, sr;
    sincos_small(tilt, &st, &ct);
    sincos_small(pan, &sp, &cp);
    sincos_small(rot, &sr, &cr);

    float F[9]  = {flip, 0, 0, 0, 1, 0, 0, 0, 1};
    float Rx[9] = {1, 0, 0, 0, ct, -st, 0, st, ct};
    float Ry[9] = {cp, 0, sp, 0, 1, 0, -sp, 0, cp};
    float RS[9] = {sc * cr, -sc * sr, 0, sc * sr, sc * cr, 0, 0, 0, 1};
    float T[9]  = {1, 0, tx, 0, 1, ty, 0, 0, 1};

    float t0[9], t1[9], t2[9], M[9];
    mat3_mul(Ry, F, t0);
    mat3_mul(Rx, t0, t1);
    mat3_mul(RS, t1, t2);
    mat3_mul(T, t2, M);

    const float* c = color_u + b * 4;
    float theta = (c[0] * 2.f - 1.f) * (10.f * DEG);
    float cth, sth;
    sincos_small(theta, &sth, &cth);
    const float a = 0.5773502691896258f;
    float K[9] = {0, -a, a, a, 0, -a, -a, a, 0};
    float Rh[9];
#pragma unroll
    for (int i = 0; i < 3; i++)
#pragma unroll
        for (int j = 0; j < 3; j++)
            Rh[i * 3 + j] = cth * (i == j ? 1.f : 0.f) + sth * K[i * 3 + j] +
                            (1.f - cth) * (1.f / 3.f);
    float sat = 1.f + (c[1] * 2.f - 1.f) * 0.4f;
    const float lum[3] = {0.299f, 0.587f, 0.114f};
    float Sm[9];
#pragma unroll
    for (int i = 0; i < 3; i++)
#pragma unroll
        for (int j = 0; j < 3; j++)
            Sm[i * 3 + j] = sat * (i == j ? 1.f : 0.f) + (1.f - sat) * lum[j];
    float bright = 1.f + (c[2] * 2.f - 1.f) * 0.1f;
    float Mc[9];
    mat3_mul(Sm, Rh, Mc);
#pragma unroll
    for (int i = 0; i < 9; i++) Mc[i] *= bright;
    float gamma = 1.f + (c[3] * 2.f - 1.f) * 0.2f;

    const float* cu = cutout_u + b * 5;
    bool apply = (cu[0] < 0.5f);
    float cwh = (0.3f + 0.2f * cu[3]) * 0.5f * 511.f;
    float chh = (0.3f + 0.2f * cu[4]) * 0.5f * 511.f;
    float ccx = cu[1] * 511.f, ccy = cu[2] * 511.f;
#pragma unroll
    for (int i = 0; i < 9; i++) p[i] = M[i];
    p[9] = gamma;
#pragma unroll
    for (int i = 0; i < 9; i++) p[10 + i] = Mc[i];
    // cutout iff jlo < jx < jhi  and  ilo < iy < ihi
    p[19] = apply ? (ccx - cwh) : 1e9f;   // jlo (never satisfied if !apply)
    p[20] = apply ? (ccx + cwh) : -1e9f;  // jhi
    p[21] = ccy - chh;                    // ilo
    p[22] = ccy + chh;                    // ihi
}

__global__ __launch_bounds__(NT, 6) void augment_main(
    const float* __restrict__ images, float* __restrict__ out,
    const float* __restrict__ geom_u, const float* __restrict__ color_u,
    const float* __restrict__ cutout_u) {
    __shared__ float spm[24];

    int b   = blockIdx.z;
    int tid = threadIdx.x;
    if (tid == 0) compute_params(b, geom_u, color_u, cutout_u, spm);
    __syncthreads();

    int lane = tid & 31;
    int w    = tid >> 5;
    int jx   = (blockIdx.x << 5) + lane;       // x (consecutive across warp)
    int iy0  = (blockIdx.y << 5) + (w << 2);   // first of 4 rows

    float m0 = spm[0], m1 = spm[1], m2 = spm[2];
    float m3 = spm[3], m4 = spm[4], m5 = spm[5];
    float m6 = spm[6], m7 = spm[7], m8 = spm[8];
    float gamma = spm[9];
    float c0 = spm[10], c1 = spm[11], c2 = spm[12];
    float c3 = spm[13], c4 = spm[14], c5 = spm[15];
    float c6 = spm[16], c7 = spm[17], c8 = spm[18];
    float jlo = spm[19], jhi = spm[20];
    float ilo = spm[21], ihi = spm[22];

    const float cc = 2.f / 511.f;
    float fjx = (float)jx;
    float X = fjx * cc - 1.f;
    float sxX = fmaf(m0, X, m2);
    float syX = fmaf(m3, X, m5);
    float szX = fmaf(m6, X, m8);

    bool cutx = (fjx > jlo) & (fjx < jhi);

    int bOff = b << 18;
    int outBase = ((bOff + (iy0 << 9)) + jx) * 3;

    float Y   = (float)iy0 * cc - 1.f;
    float fiy = (float)iy0;

#pragma unroll
    for (int k = 0; k < 4; k++) {
        float sx = fmaf(m1, Y, sxX);
        float sy = fmaf(m4, Y, syX);
        float sz = fmaf(m7, Y, szX);
        float inv = frcp_nr(sz);
        float px = fmaf(sx * inv, 255.5f, 255.5f);
        float py = fmaf(sy * inv, 255.5f, 255.5f);

        bool valid = (px >= 0.f) & (px <= 511.f) & (py >= 0.f) & (py <= 511.f);
        int x0 = min(max(__float2int_rd(px), 0), 511);
        int y0 = min(max(__float2int_rd(py), 0), 511);
        float wx = px - (float)x0;
        float wy = py - (float)y0;
        int dx3 = (x0 < 511) ? 3 : 0;
        int dyW = (y0 < 511) ? (W_ * 3) : 0;

        const float* A  = images + (bOff + (y0 << 9) + x0) * 3;
        const float* Bt = A + dyW;

        float a00 = __ldg(A + 0),        a01 = __ldg(A + 1),        a02 = __ldg(A + 2);
        float b00 = __ldg(A + dx3 + 0),  b01 = __ldg(A + dx3 + 1),  b02 = __ldg(A + dx3 + 2);
        float d00 = __ldg(Bt + 0),       d01 = __ldg(Bt + 1),       d02 = __ldg(Bt + 2);
        float e00 = __ldg(Bt + dx3 + 0), e01 = __ldg(Bt + dx3 + 1), e02 = __ldg(Bt + dx3 + 2);

        float omx = 1.f - wx, omy = 1.f - wy;
        float w00 = omx * omy, w01 = wx * omy, w10 = omx * wy, w11 = wx * wy;
        float vm = valid ? 1.f : 0.f;

        float r0 = a00 * w00 + b00 * w01 + d00 * w10 + e00 * w11;
        float r1 = a01 * w00 + b01 * w01 + d01 * w10 + e01 * w11;
        float r2 = a02 * w00 + b02 * w01 + d02 * w10 + e02 * w11;
        r0 = __saturatef(r0 * vm);
        r1 = __saturatef(r1 * vm);
        r2 = __saturatef(r2 * vm);
        r0 = fex2(gamma * flg2(r0));   // 0 -> ex2(-inf) = 0 == 0^g
        r1 = fex2(gamma * flg2(r1));
        r2 = fex2(gamma * flg2(r2));

        float o0 = __saturatef(c0 * r0 + c1 * r1 + c2 * r2);
        float o1 = __saturatef(c3 * r0 + c4 * r1 + c5 * r2);
        float o2 = __saturatef(c6 * r0 + c7 * r1 + c8 * r2);

        bool cut = cutx & (fiy > ilo) & (fiy < ihi);
        if (cut) { o0 = 0.f; o1 = 0.f; o2 = 0.f; }

        float* op = out + outBase;
        op[0] = o0;
        op[1] = o1;
        op[2] = o2;

        Y += cc;
        fiy += 1.f;
        outBase += W_ * 3;
    }
}

extern "C" void kernel_launch(void* const* d_in, const int* in_sizes, int n_in,
                              void* d_out, int out_size) {
    const float* images   = (const float*)d_in[0];
    const float* geom_u   = (const float*)d_in[1];
    const float* color_u  = (const float*)d_in[2];
    const float* cutout_u = (const float*)d_in[3];
    float* out = (float*)d_out;

    dim3 grid(W_ / 32, H_ / 32, B_);
    augment_main<<<grid, NT>>>(images, out, geom_u, color_u, cutout_u);
}

// round 17
// speedup vs baseline: 1.0718x; 1.0114x over previous
#include <cuda_runtime.h>
#include <math.h>

#define B_  32
#define H_  512
#define W_  512
#define DEG 0.017453292519943295f
#define NT  256     // 8 warps; warp w handles rows [w*4, w*4+4) of a 32x32 tile

__device__ __forceinline__ float frcp_nr(float x) {
    float y;
    asm("rcp.approx.f32 %0, %1;" : "=f"(y) : "f"(x));
    return y * fmaf(-x, y, 2.0f);   // one Newton step -> ~1 ulp
}
__device__ __forceinline__ float flg2(float x) {
    float y;
    asm("lg2.approx.f32 %0, %1;" : "=f"(y) : "f"(x));
    return y;
}
__device__ __forceinline__ float fex2(float x) {
    float y;
    asm("ex2.approx.f32 %0, %1;" : "=f"(y) : "f"(x));
    return y;
}

// Taylor sin/cos for |x| <= 0.262 rad: err ~1.6e-8 / 4e-10 -- better than sinf.
__device__ __forceinline__ void sincos_small(float x, float* s, float* c) {
    float x2 = x * x;
    *s = x * fmaf(x2, fmaf(x2, fmaf(x2, -1.984126984e-4f, 8.333333333e-3f),
                           -1.666666667e-1f), 1.f);
    *c = fmaf(x2, fmaf(x2, fmaf(x2, -1.388888889e-3f, 4.166666667e-2f),
                       -5.e-1f), 1.f);
}

__device__ __forceinline__ void mat3_mul(const float* A, const float* Bm, float* C) {
#pragma unroll
    for (int i = 0; i < 3; i++)
#pragma unroll
        for (int j = 0; j < 3; j++) {
            float s = 0.f;
#pragma unroll
            for (int k = 0; k < 3; k++) s += A[i * 3 + k] * Bm[k * 3 + j];
            C[i * 3 + j] = s;
        }
}

// Per-block param computation (thread 0); ~120 instrs, hidden by other
// resident blocks. Layout: 0..8 M, 9 gamma, 10..18 Mc,
// 19 jlo, 20 jhi, 21 ilo, 22 ihi (pixel-space cutout bounds, exclusive <)
__device__ void compute_params(int b,
                               const float* __restrict__ geom_u,
                               const float* __restrict__ color_u,
                               const float* __restrict__ cutout_u,
                               float* __restrict__ p) {
    const float* g = geom_u + b * 8;
    float flip = g[0] > 0.5f ? -1.f : 1.f;
    float tilt = (g[1] * 2.f - 1.f) * (15.f * DEG);
    float pan  = (g[2] * 2.f - 1.f) * (15.f * DEG);
    float rot  = (g[3] * 2.f - 1.f) * (15.f * DEG);
    float sc   = 1.f + (g[4] * 2.f - 1.f) * 0.1f;
    float tx   = (g[5] * 2.f - 1.f) * 0.2f;
    float ty   = (g[6] * 2.f - 1.f) * 0.2f;

    float ct, st, cp, sp, cr, sr;
    sincos_small(tilt, &st, &ct);
    sincos_small(pan, &sp, &cp);
    sincos_small(rot, &sr, &cr);

    float F[9]  = {flip, 0, 0, 0, 1, 0, 0, 0, 1};
    float Rx[9] = {1, 0, 0, 0, ct, -st, 0, st, ct};
    float Ry[9] = {cp, 0, sp, 0, 1, 0, -sp, 0, cp};
    float RS[9] = {sc * cr, -sc * sr, 0, sc * sr, sc * cr, 0, 0, 0, 1};
    float T[9]  = {1, 0, tx, 0, 1, ty, 0, 0, 1};

    float t0[9], t1[9], t2[9], M[9];
    mat3_mul(Ry, F, t0);
    mat3_mul(Rx, t0, t1);
    mat3_mul(RS, t1, t2);
    mat3_mul(T, t2, M);

    const float* c = color_u + b * 4;
    float theta = (c[0] * 2.f - 1.f) * (10.f * DEG);
    float cth, sth;
    sincos_small(theta, &sth, &cth);
    const float a = 0.5773502691896258f;
    float K[9] = {0, -a, a, a, 0, -a, -a, a, 0};
    float Rh[9];
#pragma unroll
    for (int i = 0; i < 3; i++)
#pragma unroll
        for (int j = 0; j < 3; j++)
            Rh[i * 3 + j] = cth * (i == j ? 1.f : 0.f) + sth * K[i * 3 + j] +
                            (1.f - cth) * (1.f / 3.f);
    float sat = 1.f + (c[1] * 2.f - 1.f) * 0.4f;
    const float lum[3] = {0.299f, 0.587f, 0.114f};
    float Sm[9];
#pragma unroll
    for (int i = 0; i < 3; i++)
#pragma unroll
        for (int j = 0; j < 3; j++)
            Sm[i * 3 + j] = sat * (i == j ? 1.f : 0.f) + (1.f - sat) * lum[j];
    float bright = 1.f + (c[2] * 2.f - 1.f) * 0.1f;
    float Mc[9];
    mat3_mul(Sm, Rh, Mc);
#pragma unroll
    for (int i = 0; i < 9; i++) Mc[i] *= bright;
    float gamma = 1.f + (c[3] * 2.f - 1.f) * 0.2f;

    const float* cu = cutout_u + b * 5;
    bool apply = (cu[0] < 0.5f);
    float cwh = (0.3f + 0.2f * cu[3]) * 0.5f * 511.f;
    float chh = (0.3f + 0.2f * cu[4]) * 0.5f * 511.f;
    float ccx = cu[1] * 511.f, ccy = cu[2] * 511.f;
#pragma unroll
    for (int i = 0; i < 9; i++) p[i] = M[i];
    p[9] = gamma;
#pragma unroll
    for (int i = 0; i < 9; i++) p[10 + i] = Mc[i];
    // cutout iff jlo < jx < jhi  and  ilo < iy < ihi
    p[19] = apply ? (ccx - cwh) : 1e9f;   // jlo (never satisfied if !apply)
    p[20] = apply ? (ccx + cwh) : -1e9f;  // jhi
    p[21] = ccy - chh;                    // ilo
    p[22] = ccy + chh;                    // ihi
}

__global__ __launch_bounds__(NT, 6) void augment_main(
    const float* __restrict__ images, float* __restrict__ out,
    const float* __restrict__ geom_u, const float* __restrict__ color_u,
    const float* __restrict__ cutout_u) {
    __shared__ float spm[24];

    int b   = blockIdx.z;
    int tid = threadIdx.x;
    if (tid == 0) compute_params(b, geom_u, color_u, cutout_u, spm);
    __syncthreads();

    int lane = tid & 31;
    int w    = tid >> 5;
    int jx   = (blockIdx.x << 5) + lane;       // x (consecutive across warp)
    int iy0  = (blockIdx.y << 5) + (w << 2);   // first of 4 rows

    float m0 = spm[0], m1 = spm[1], m2 = spm[2];
    float m3 = spm[3], m4 = spm[4], m5 = spm[5];
    float m6 = spm[6], m7 = spm[7], m8 = spm[8];
    float gamma = spm[9];
    float c0 = spm[10], c1 = spm[11], c2 = spm[12];
    float c3 = spm[13], c4 = spm[14], c5 = spm[15];
    float c6 = spm[16], c7 = spm[17], c8 = spm[18];
    float jlo = spm[19], jhi = spm[20];
    float ilo = spm[21], ihi = spm[22];

    const float cc = 2.f / 511.f;
    float fjx = (float)jx;
    float X = fjx * cc - 1.f;
    float sxX = fmaf(m0, X, m2);
    float syX = fmaf(m3, X, m5);
    float szX = fmaf(m6, X, m8);

    bool cutx = (fjx > jlo) & (fjx < jhi);

    int bOff = b << 18;
    int outBase = ((bOff + (iy0 << 9)) + jx) * 3;

    float Y   = (float)iy0 * cc - 1.f;
    float fiy = (float)iy0;

#pragma unroll
    for (int k = 0; k < 4; k++) {
        float sx = fmaf(m1, Y, sxX);
        float sy = fmaf(m4, Y, syX);
        float sz = fmaf(m7, Y, szX);
        float inv = frcp_nr(sz);
        float px = fmaf(sx * inv, 255.5f, 255.5f);
        float py = fmaf(sy * inv, 255.5f, 255.5f);

        bool valid = (px >= 0.f) & (px <= 511.f) & (py >= 0.f) & (py <= 511.f);
        int x0 = min(max(__float2int_rd(px), 0), 511);
        int y0 = min(max(__float2int_rd(py), 0), 511);
        float wx = px - (float)x0;
        float wy = py - (float)y0;
        int dx3 = (x0 < 511) ? 3 : 0;
        int dyW = (y0 < 511) ? (W_ * 3) : 0;

        const float* A  = images + (bOff + (y0 << 9) + x0) * 3;
        const float* Bt = A + dyW;

        float a00 = __ldg(A + 0),        a01 = __ldg(A + 1),        a02 = __ldg(A + 2);
        float b00 = __ldg(A + dx3 + 0),  b01 = __ldg(A + dx3 + 1),  b02 = __ldg(A + dx3 + 2);
        float d00 = __ldg(Bt + 0),       d01 = __ldg(Bt + 1),       d02 = __ldg(Bt + 2);
        float e00 = __ldg(Bt + dx3 + 0), e01 = __ldg(Bt + dx3 + 1), e02 = __ldg(Bt + dx3 + 2);

        float omx = 1.f - wx, omy = 1.f - wy;
        float w00 = omx * omy, w01 = wx * omy, w10 = omx * wy, w11 = wx * wy;
        float vm = valid ? 1.f : 0.f;

        float r0 = a00 * w00 + b00 * w01 + d00 * w10 + e00 * w11;
        float r1 = a01 * w00 + b01 * w01 + d01 * w10 + e01 * w11;
        float r2 = a02 * w00 + b02 * w01 + d02 * w10 + e02 * w11;
        r0 = __saturatef(r0 * vm);
        r1 = __saturatef(r1 * vm);
        r2 = __saturatef(r2 * vm);
        r0 = fex2(gamma * flg2(r0));   // 0 -> ex2(-inf) = 0 == 0^g
        r1 = fex2(gamma * flg2(r1));
        r2 = fex2(gamma * flg2(r2));

        float o0 = __saturatef(c0 * r0 + c1 * r1 + c2 * r2);
        float o1 = __saturatef(c3 * r0 + c4 * r1 + c5 * r2);
        float o2 = __saturatef(c6 * r0 + c7 * r1 + c8 * r2);

        bool cut = cutx & (fiy > ilo) & (fiy < ihi);
        if (cut) { o0 = 0.f; o1 = 0.f; o2 = 0.f; }

        // streaming stores: output is write-once, never re-read ->
        // evict-first in L2, keep the image read-set resident.
        float* op = out + outBase;
        __stcs(op + 0, o0);
        __stcs(op + 1, o1);
        __stcs(op + 2, o2);

        Y += cc;
        fiy += 1.f;
        outBase += W_ * 3;
    }
}

extern "C" void kernel_launch(void* const* d_in, const int* in_sizes, int n_in,
                              void* d_out, int out_size) {
    const float* images   = (const float*)d_in[0];
    const float* geom_u   = (const float*)d_in[1];
    const float* color_u  = (const float*)d_in[2];
    const float* cutout_u = (const float*)d_in[3];
    float* out = (float*)d_out;

    dim3 grid(W_ / 32, H_ / 32, B_);
    augment_main<<<grid, NT>>>(images, out, geom_u, color_u, cutout_u);
}